// round 5
// baseline (speedup 1.0000x reference)
#include <cuda_runtime.h>

// ---------------- problem constants ----------------
#define BB    64
#define MAXV  200
#define PP    40     // codes per visit
#define DOTH  57
#define KK    100
#define NCODE 507    // NUM_CODE + 1
#define TT    9      // time steps per block (198 = 22 * 9)
#define NTILE 22
#define TOUT  198
#define HID   256

// Per-batch tgt contributions (time-invariant): tgt[b] @ Wf[507:607], @ Wb[507:607]
__device__ float g_tgtF[BB * HID];
__device__ float g_tgtB[BB * HID];

// ---------------------------------------------------------------------------
// Kernel 1: tgt01[b,k] = (weight_idx[k] in target[b]) ? 0 : 1
//           g_tgtF[b][j] = sum_k tgt01 * Wf[(507+k)][j]   (same for Wb)
// ---------------------------------------------------------------------------
__global__ __launch_bounds__(256) void tgt_kernel(
    const int* __restrict__ target, const int* __restrict__ widx,
    const float* __restrict__ Wf, const float* __restrict__ Wb)
{
    __shared__ int s_t[10];
    __shared__ int s_keep[KK];
    const int b = blockIdx.x;
    const int j = threadIdx.x;
    if (j < 10) s_t[j] = target[b * 10 + j];
    __syncthreads();
    if (j < KK) {
        int w = widx[j];
        int keep = 1;
        #pragma unroll
        for (int q = 0; q < 10; q++) keep &= (s_t[q] != w);
        s_keep[j] = keep;
    }
    __syncthreads();
    float aF = 0.f, aB = 0.f;
    for (int k = 0; k < KK; k++) {
        if (s_keep[k]) {
            aF += Wf[(507 + k) * HID + j];
            aB += Wb[(507 + k) * HID + j];
        }
    }
    g_tgtF[b * HID + j] = aF;
    g_tgtB[b * HID + j] = aB;
}

// ---------------------------------------------------------------------------
// Dedup: multi_hot collapses duplicate codes. For each (r,p), keep code only
// if no earlier p' in the same row has the same code. Output -1 for skips.
// ---------------------------------------------------------------------------
__device__ __forceinline__ void dedup_codes(const int* __restrict__ s_codes,
                                            int* __restrict__ s_out, int j)
{
    for (int idx = j; idx < TT * PP; idx += 256) {
        int p = idx % PP;
        int base = idx - p;
        int c = s_codes[idx];
        int take = 1;
        for (int q = 0; q < p; q++) take &= (s_codes[base + q] != c);
        s_out[idx] = take ? c : -1;
    }
}

// ---------------------------------------------------------------------------
// Main kernel: one block = (batch b, 9 consecutive output time steps).
// Thread j owns output column j across all 9 rows (register tiling: every
// dense weight element loaded once, used 9x).
// ---------------------------------------------------------------------------
__global__ __launch_bounds__(256, 4) void main_kernel(
    const int*   __restrict__ code,   const float* __restrict__ others,
    const int*   __restrict__ length,
    const float* __restrict__ Wf, const float* __restrict__ bf,
    const float* __restrict__ Wb, const float* __restrict__ bb,
    const float* __restrict__ W0, const float* __restrict__ b0,
    const float* __restrict__ W1, const float* __restrict__ b1,
    float* __restrict__ outF, float* __restrict__ outB, float* __restrict__ outV)
{
    __shared__ __align__(16) float s_h1[TT * HID];     // 9216 B
    __shared__ int   s_codes[TT * PP];                 // 1440 B
    __shared__ int   s_codes2[TT * PP];                // 1440 B (dedup'd)
    __shared__ float s_sc[TT * 64];                    // dense scalars
    __shared__ float s_red[8 * TT];
    __shared__ float s_rsq[TT];

    const int b  = blockIdx.y;
    const int t0 = blockIdx.x * TT;
    const int j  = threadIdx.x;
    const int L  = length[b];
    const float* oth = others + b * MAXV * DOTH;
    const int*   cod = code   + b * MAXV * PP;

    float acc[TT];

    // ============================ FORWARD ============================
    // x_forward[b,t] = [codes(t), tgt, oth(t)[0:27], oth(t)[37:57], oth(t)[27:37]] @ Wf + bf
    for (int idx = j; idx < TT * PP; idx += 256) {
        int r = idx / PP, p = idx - r * PP;
        s_codes[idx] = cod[(t0 + r) * PP + p];
    }
    for (int idx = j; idx < TT * 57; idx += 256) {
        int r = idx / 57, i = idx - r * 57;
        int col = (i < 27) ? i : ((i < 47) ? i + 10 : i - 20);
        s_sc[r * 64 + i] = oth[(t0 + r) * DOTH + col];
    }
    __syncthreads();
    dedup_codes(s_codes, s_codes2, j);
    __syncthreads();
    {
        float base = bf[j] + g_tgtF[b * HID + j];
        #pragma unroll
        for (int r = 0; r < TT; r++) acc[r] = base;
    }
    #pragma unroll
    for (int r = 0; r < TT; r++) {
        const int* cp = s_codes2 + r * PP;
        #pragma unroll 8
        for (int p = 0; p < PP; p++) {
            int c = cp[p];
            if (c >= 0) acc[r] += Wf[c * HID + j];
        }
    }
    for (int i = 0; i < 57; i++) {
        float w = Wf[(607 + i) * HID + j];
        #pragma unroll
        for (int r = 0; r < TT; r++) acc[r] += s_sc[r * 64 + i] * w;
    }
    #pragma unroll
    for (int r = 0; r < TT; r++)
        outF[(b * TOUT + t0 + r) * HID + j] = acc[r];

    // ============================ BACKWARD ============================
    // feature_backward[b,t] = feature[b, rf(t)], rf = (t<L) ? L-1-t : t
    // interval_backward[b,t] = (t==0) ? 0 : oth[ri][27:37], ri = (t-1<L) ? L-t : t-1
    __syncthreads();
    for (int idx = j; idx < TT * PP; idx += 256) {
        int r = idx / PP, p = idx - r * PP;
        int t = t0 + r;
        int rf = (t < L) ? (L - 1 - t) : t;
        s_codes[idx] = cod[rf * PP + p];
    }
    for (int idx = j; idx < TT * 57; idx += 256) {
        int r = idx / 57, i = idx - r * 57;
        int t = t0 + r;
        float v;
        if (i < 47) {
            int rf = (t < L) ? (L - 1 - t) : t;
            int col = (i < 27) ? i : i + 10;
            v = oth[rf * DOTH + col];
        } else {
            if (t == 0) v = 0.f;
            else {
                int ri = ((t - 1) < L) ? (L - t) : (t - 1);
                v = oth[ri * DOTH + (i - 20)];
            }
        }
        s_sc[r * 64 + i] = v;
    }
    __syncthreads();
    dedup_codes(s_codes, s_codes2, j);
    __syncthreads();
    {
        float base = bb[j] + g_tgtB[b * HID + j];
        #pragma unroll
        for (int r = 0; r < TT; r++) acc[r] = base;
    }
    #pragma unroll
    for (int r = 0; r < TT; r++) {
        const int* cp = s_codes2 + r * PP;
        #pragma unroll 8
        for (int p = 0; p < PP; p++) {
            int c = cp[p];
            if (c >= 0) acc[r] += Wb[c * HID + j];
        }
    }
    for (int i = 0; i < 57; i++) {
        float w = Wb[(607 + i) * HID + j];
        #pragma unroll
        for (int r = 0; r < TT; r++) acc[r] += s_sc[r * 64 + i] * w;
    }
    #pragma unroll
    for (int r = 0; r < TT; r++)
        outB[(b * TOUT + t0 + r) * HID + j] = acc[r];

    // ============================ FV (2-layer MLP + L2 norm) ============================
    // x[b,t] = [codes(t+1), oth(t+1)[37:57], oth(t+1)[27:37], oth(t+2)[27:37], oth(t+1)[19:27]]
    // h1 = relu(x@W0+b0); h = h1@W1+b1; fv = h/||h|| * (t < L-2)
    __syncthreads();
    if (t0 < L - 2) {
        for (int idx = j; idx < TT * PP; idx += 256) {
            int r = idx / PP, p = idx - r * PP;
            s_codes[idx] = cod[(t0 + r + 1) * PP + p];
        }
        for (int idx = j; idx < TT * 48; idx += 256) {
            int r = idx / 48, i = idx - r * 48;
            int t = t0 + r;
            int row, col;
            if (i < 20)      { row = t + 1; col = 37 + i; }
            else if (i < 30) { row = t + 1; col = i + 7;  }   // 27 + (i-20)
            else if (i < 40) { row = t + 2; col = i - 3;  }   // 27 + (i-30)
            else             { row = t + 1; col = i - 21; }   // 19 + (i-40)
            s_sc[r * 64 + i] = oth[row * DOTH + col];
        }
        __syncthreads();
        dedup_codes(s_codes, s_codes2, j);
        __syncthreads();
        {
            float base = b0[j];
            #pragma unroll
            for (int r = 0; r < TT; r++) acc[r] = base;
        }
        #pragma unroll
        for (int r = 0; r < TT; r++) {
            const int* cp = s_codes2 + r * PP;
            #pragma unroll 8
            for (int p = 0; p < PP; p++) {
                int c = cp[p];
                if (c >= 0) acc[r] += W0[c * HID + j];
            }
        }
        for (int i = 0; i < 48; i++) {
            float w = W0[(507 + i) * HID + j];
            #pragma unroll
            for (int r = 0; r < TT; r++) acc[r] += s_sc[r * 64 + i] * w;
        }
        #pragma unroll
        for (int r = 0; r < TT; r++) s_h1[r * HID + j] = fmaxf(acc[r], 0.f);
        __syncthreads();

        // layer 1: h = relu(.) @ W1 + b1, register-tiled over TT rows
        {
            float base = b1[j];
            #pragma unroll
            for (int r = 0; r < TT; r++) acc[r] = base;
        }
        for (int i = 0; i < HID; i += 4) {
            float w0 = W1[(i + 0) * HID + j];
            float w1v = W1[(i + 1) * HID + j];
            float w2 = W1[(i + 2) * HID + j];
            float w3 = W1[(i + 3) * HID + j];
            #pragma unroll
            for (int r = 0; r < TT; r++) {
                float4 h = *(const float4*)&s_h1[r * HID + i];
                acc[r] = fmaf(h.x, w0, fmaf(h.y, w1v, fmaf(h.z, w2, fmaf(h.w, w3, acc[r]))));
            }
        }

        // L2 norm per row: block reduce of sum(h^2)
        #pragma unroll
        for (int r = 0; r < TT; r++) {
            float v = acc[r] * acc[r];
            v += __shfl_xor_sync(0xffffffffu, v, 16);
            v += __shfl_xor_sync(0xffffffffu, v, 8);
            v += __shfl_xor_sync(0xffffffffu, v, 4);
            v += __shfl_xor_sync(0xffffffffu, v, 2);
            v += __shfl_xor_sync(0xffffffffu, v, 1);
            if ((j & 31) == 0) s_red[(j >> 5) * TT + r] = v;
        }
        __syncthreads();
        if (j < TT) {
            float s = 0.f;
            #pragma unroll
            for (int w = 0; w < 8; w++) s += s_red[w * TT + j];
            float inv = rsqrtf(s);
            inv = inv * (1.5f - 0.5f * s * inv * inv);  // one Newton step for accuracy
            s_rsq[j] = inv;
        }
        __syncthreads();
        #pragma unroll
        for (int r = 0; r < TT; r++) {
            int t = t0 + r;
            float m = (t < L - 2) ? s_rsq[r] : 0.f;
            outV[(b * TOUT + t) * HID + j] = acc[r] * m;
        }
    } else {
        // fully masked tile: fv rows are exactly zero
        #pragma unroll
        for (int r = 0; r < TT; r++)
            outV[(b * TOUT + t0 + r) * HID + j] = 0.f;
    }
}

// ---------------------------------------------------------------------------
extern "C" void kernel_launch(void* const* d_in, const int* in_sizes, int n_in,
                              void* d_out, int out_size)
{
    (void)in_sizes; (void)n_in; (void)out_size;
    const int*   code    = (const int*)  d_in[0];
    const float* others  = (const float*)d_in[1];
    const int*   length  = (const int*)  d_in[2];
    const int*   target  = (const int*)  d_in[3];
    const int*   widx    = (const int*)  d_in[4];
    const float* Wf      = (const float*)d_in[5];
    const float* bf      = (const float*)d_in[6];
    const float* Wb      = (const float*)d_in[7];
    const float* bb      = (const float*)d_in[8];
    const float* W0      = (const float*)d_in[9];
    const float* b0      = (const float*)d_in[10];
    const float* W1      = (const float*)d_in[11];
    const float* b1      = (const float*)d_in[12];

    float* outF = (float*)d_out;
    float* outB = outF + (size_t)BB * TOUT * HID;
    float* outV = outB + (size_t)BB * TOUT * HID;

    tgt_kernel<<<BB, 256>>>(target, widx, Wf, Wb);
    main_kernel<<<dim3(NTILE, BB), 256>>>(code, others, length,
                                          Wf, bf, Wb, bb, W0, b0, W1, b1,
                                          outF, outB, outV);
}

// round 6
// speedup vs baseline: 1.4508x; 1.4508x over previous
#include <cuda_runtime.h>

typedef unsigned long long u64;

// ---------------- problem constants ----------------
#define BB    64
#define MAXV  200
#define PP    40     // codes per visit
#define DOTH  57
#define KK    100
#define TT    10     // time steps per block (20 * 10 = 200 >= 198)
#define NTILE 20
#define TOUT  198
#define HID   256
#define RP    5      // rows per group in phase A (2 groups)

// Per-batch tgt contributions (time-invariant)
__device__ float g_tgtF[BB * HID];
__device__ float g_tgtB[BB * HID];

// ---------------- packed f32x2 helpers ----------------
__device__ __forceinline__ u64 f2fma(u64 a, u64 b, u64 c) {
    u64 d; asm("fma.rn.f32x2 %0,%1,%2,%3;" : "=l"(d) : "l"(a), "l"(b), "l"(c)); return d;
}
__device__ __forceinline__ u64 f2add(u64 a, u64 b) {
    u64 d; asm("add.rn.f32x2 %0,%1,%2;" : "=l"(d) : "l"(a), "l"(b)); return d;
}
__device__ __forceinline__ u64 dup2(float v) {
    u64 d; asm("mov.b64 %0,{%1,%1};" : "=l"(d) : "f"(v)); return d;
}
__device__ __forceinline__ void unpack2(u64 v, float& x, float& y) {
    asm("mov.b64 {%0,%1},%2;" : "=f"(x), "=f"(y) : "l"(v));
}
__device__ __forceinline__ u64 ldg2(const float* __restrict__ p) {
    return *reinterpret_cast<const u64*>(p);
}

// ---------------------------------------------------------------------------
// Kernel 1: per-batch tgt @ Wf[507:607] / Wb[507:607]
// ---------------------------------------------------------------------------
__global__ __launch_bounds__(256) void tgt_kernel(
    const int* __restrict__ target, const int* __restrict__ widx,
    const float* __restrict__ Wf, const float* __restrict__ Wb)
{
    __shared__ int s_t[10];
    __shared__ int s_keep[KK];
    const int b = blockIdx.x;
    const int j = threadIdx.x;
    if (j < 10) s_t[j] = target[b * 10 + j];
    __syncthreads();
    if (j < KK) {
        int w = widx[j];
        int keep = 1;
        #pragma unroll
        for (int q = 0; q < 10; q++) keep &= (s_t[q] != w);
        s_keep[j] = keep;
    }
    __syncthreads();
    float aF = 0.f, aB = 0.f;
    for (int k = 0; k < KK; k++) {
        if (s_keep[k]) {
            aF += Wf[(507 + k) * HID + j];
            aB += Wb[(507 + k) * HID + j];
        }
    }
    g_tgtF[b * HID + j] = aF;
    g_tgtB[b * HID + j] = aB;
}

// ---------------------------------------------------------------------------
// Dedup: multi_hot collapses duplicate codes within a row. -1 = skip.
// ---------------------------------------------------------------------------
__device__ __forceinline__ void dedup_codes(const int* __restrict__ s_codes,
                                            int* __restrict__ s_out, int j)
{
    for (int idx = j; idx < TT * PP; idx += 256) {
        int p = idx % PP;
        int base = idx - p;
        int c = s_codes[idx];
        int take = 1;
        for (int q = 0; q < p; q++) take &= (s_codes[base + q] != c);
        s_out[idx] = take ? c : -1;
    }
}

// ---------------------------------------------------------------------------
// Gather (sparse codes) + dense features, packed f32x2, RP rows per thread.
// ---------------------------------------------------------------------------
__device__ __forceinline__ void gather_dense(
    u64* __restrict__ acc, const int* __restrict__ s_codes2,
    const u64* __restrict__ s_sc2, const float* __restrict__ W,
    int denseRow0, int nd, int g, int c0)
{
    // sparse gathers: predicated LDG.64 + packed add (2 accumulators / row)
    #pragma unroll
    for (int lr = 0; lr < RP; lr++) {
        const int* cp = s_codes2 + (g * RP + lr) * PP;
        u64 a0 = acc[lr], a1 = 0ull;
        #pragma unroll 10
        for (int p = 0; p < PP; p += 2) {
            int ca = cp[p];
            int cb = cp[p + 1];
            if (ca >= 0) a0 = f2add(a0, ldg2(W + ca * HID + c0));
            if (cb >= 0) a1 = f2add(a1, ldg2(W + cb * HID + c0));
        }
        acc[lr] = f2add(a0, a1);
    }
    // dense part: pairs of feature columns, LDS.128 on duplicated scalars
    int i = 0;
    for (; i + 1 < nd; i += 2) {
        u64 w0 = ldg2(W + (denseRow0 + i) * HID + c0);
        u64 w1 = ldg2(W + (denseRow0 + i + 1) * HID + c0);
        #pragma unroll
        for (int lr = 0; lr < RP; lr++) {
            ulonglong2 s = *reinterpret_cast<const ulonglong2*>(&s_sc2[(g * RP + lr) * 64 + i]);
            acc[lr] = f2fma(s.x, w0, acc[lr]);
            acc[lr] = f2fma(s.y, w1, acc[lr]);
        }
    }
    if (i < nd) {
        u64 w0 = ldg2(W + (denseRow0 + i) * HID + c0);
        #pragma unroll
        for (int lr = 0; lr < RP; lr++)
            acc[lr] = f2fma(s_sc2[(g * RP + lr) * 64 + i], w0, acc[lr]);
    }
}

// ---------------------------------------------------------------------------
// Main kernel. Phase A (F/B/FV-layer0): 2 groups x 5 rows, 128 col-pairs.
// Phase B (W1 GEMM): 128 col-pairs x 2 i-halves, all 10 rows in registers.
// ---------------------------------------------------------------------------
__global__ __launch_bounds__(256, 5) void main_kernel(
    const int*   __restrict__ code,   const float* __restrict__ others,
    const int*   __restrict__ length,
    const float* __restrict__ Wf, const float* __restrict__ bf,
    const float* __restrict__ Wb, const float* __restrict__ bb,
    const float* __restrict__ W0, const float* __restrict__ b0,
    const float* __restrict__ W1, const float* __restrict__ b1,
    float* __restrict__ outF, float* __restrict__ outB, float* __restrict__ outV)
{
    // one aliased region: {codes(1600) | codes2(1600) | sc2(5120)}  ->
    //                     {h1 duplicated (20480)} -> {partials (10240)}
    __shared__ __align__(16) char s_mem[TT * HID * 8];
    __shared__ float s_red[4 * TT];
    __shared__ float s_rsq[TT];

    int* s_codes  = (int*)s_mem;
    int* s_codes2 = (int*)(s_mem + TT * PP * 4);
    u64* s_sc2    = (u64*)(s_mem + 2 * TT * PP * 4);
    u64* s_h1d    = (u64*)s_mem;
    u64* s_part   = (u64*)s_mem;

    const int b  = blockIdx.y;
    const int t0 = blockIdx.x * TT;
    const int j  = threadIdx.x;
    const int g  = j >> 7;        // group / i-half
    const int jc = j & 127;       // column pair id
    const int c0 = 2 * jc;
    const int L  = length[b];
    const float* oth = others + (size_t)b * MAXV * DOTH;
    const int*   cod = code   + (size_t)b * MAXV * PP;

    u64 acc[RP];

    // ============================ FORWARD ============================
    for (int idx = j; idx < TT * PP; idx += 256) {
        int r = idx / PP, p = idx - r * PP;
        s_codes[idx] = cod[(t0 + r) * PP + p];
    }
    for (int idx = j; idx < TT * 57; idx += 256) {
        int r = idx / 57, i = idx - r * 57;
        int col = (i < 27) ? i : ((i < 47) ? i + 10 : i - 20);
        s_sc2[r * 64 + i] = dup2(oth[(t0 + r) * DOTH + col]);
    }
    __syncthreads();
    dedup_codes(s_codes, s_codes2, j);
    __syncthreads();
    {
        u64 base = f2add(ldg2(bf + c0), ldg2(&g_tgtF[b * HID + c0]));
        #pragma unroll
        for (int lr = 0; lr < RP; lr++) acc[lr] = base;
    }
    gather_dense(acc, s_codes2, s_sc2, Wf, 607, 57, g, c0);
    #pragma unroll
    for (int lr = 0; lr < RP; lr++) {
        int t = t0 + g * RP + lr;
        if (t < TOUT)
            *reinterpret_cast<u64*>(&outF[((size_t)b * TOUT + t) * HID + c0]) = acc[lr];
    }

    // ============================ BACKWARD ============================
    __syncthreads();
    for (int idx = j; idx < TT * PP; idx += 256) {
        int r = idx / PP, p = idx - r * PP;
        int t = t0 + r;
        int rf = (t < L) ? (L - 1 - t) : t;
        s_codes[idx] = cod[rf * PP + p];
    }
    for (int idx = j; idx < TT * 57; idx += 256) {
        int r = idx / 57, i = idx - r * 57;
        int t = t0 + r;
        float v;
        if (i < 47) {
            int rf = (t < L) ? (L - 1 - t) : t;
            int col = (i < 27) ? i : i + 10;
            v = oth[rf * DOTH + col];
        } else {
            if (t == 0) v = 0.f;
            else {
                int ri = ((t - 1) < L) ? (L - t) : (t - 1);
                v = oth[ri * DOTH + (i - 20)];
            }
        }
        s_sc2[r * 64 + i] = dup2(v);
    }
    __syncthreads();
    dedup_codes(s_codes, s_codes2, j);
    __syncthreads();
    {
        u64 base = f2add(ldg2(bb + c0), ldg2(&g_tgtB[b * HID + c0]));
        #pragma unroll
        for (int lr = 0; lr < RP; lr++) acc[lr] = base;
    }
    gather_dense(acc, s_codes2, s_sc2, Wb, 607, 57, g, c0);
    #pragma unroll
    for (int lr = 0; lr < RP; lr++) {
        int t = t0 + g * RP + lr;
        if (t < TOUT)
            *reinterpret_cast<u64*>(&outB[((size_t)b * TOUT + t) * HID + c0]) = acc[lr];
    }

    // ============================ FV ============================
    __syncthreads();
    if (t0 < L - 2) {
        for (int idx = j; idx < TT * PP; idx += 256) {
            int r = idx / PP, p = idx - r * PP;
            int tv = min(t0 + r, TOUT - 1);
            s_codes[idx] = cod[(tv + 1) * PP + p];
        }
        for (int idx = j; idx < TT * 48; idx += 256) {
            int r = idx / 48, i = idx - r * 48;
            int tv = min(t0 + r, TOUT - 1);
            int row, col;
            if (i < 20)      { row = tv + 1; col = 37 + i; }
            else if (i < 30) { row = tv + 1; col = i + 7;  }
            else if (i < 40) { row = tv + 2; col = i - 3;  }
            else             { row = tv + 1; col = i - 21; }
            s_sc2[r * 64 + i] = dup2(oth[row * DOTH + col]);
        }
        __syncthreads();
        dedup_codes(s_codes, s_codes2, j);
        __syncthreads();
        {
            u64 base = ldg2(b0 + c0);
            #pragma unroll
            for (int lr = 0; lr < RP; lr++) acc[lr] = base;
        }
        gather_dense(acc, s_codes2, s_sc2, W0, 507, 48, g, c0);

        // relu -> duplicated h1 into the aliased region (after all reads done)
        __syncthreads();
        #pragma unroll
        for (int lr = 0; lr < RP; lr++) {
            float x, y; unpack2(acc[lr], x, y);
            int r = g * RP + lr;
            s_h1d[r * HID + c0]     = dup2(fmaxf(x, 0.f));
            s_h1d[r * HID + c0 + 1] = dup2(fmaxf(y, 0.f));
        }
        __syncthreads();

        // W1 GEMM: thread = (col-pair jc, i-half g); all TT rows in registers.
        u64 acc2[TT];
        {
            u64 init = (g == 0) ? ldg2(b1 + c0) : 0ull;
            #pragma unroll
            for (int r = 0; r < TT; r++) acc2[r] = init;
        }
        {
            const float* Wp = W1 + (size_t)(g * 128) * HID + c0;
            const u64*   hp = s_h1d + g * 128;
            for (int i = 0; i < 128; i += 2) {
                u64 w0 = ldg2(Wp + (size_t)i * HID);
                u64 w1 = ldg2(Wp + (size_t)(i + 1) * HID);
                #pragma unroll
                for (int r = 0; r < TT; r++) {
                    ulonglong2 hh = *reinterpret_cast<const ulonglong2*>(&hp[r * HID + i]);
                    acc2[r] = f2fma(hh.x, w0, acc2[r]);
                    acc2[r] = f2fma(hh.y, w1, acc2[r]);
                }
            }
        }
        // combine i-halves (deterministic order: half0 + half1)
        __syncthreads();     // all reads of s_h1d done before overwrite
        if (g == 1) {
            #pragma unroll
            for (int r = 0; r < TT; r++) s_part[r * 128 + jc] = acc2[r];
        }
        __syncthreads();
        if (g == 0) {
            #pragma unroll
            for (int r = 0; r < TT; r++) {
                acc2[r] = f2add(acc2[r], s_part[r * 128 + jc]);
                float x, y; unpack2(acc2[r], x, y);
                float v = x * x + y * y;
                v += __shfl_xor_sync(0xffffffffu, v, 16);
                v += __shfl_xor_sync(0xffffffffu, v, 8);
                v += __shfl_xor_sync(0xffffffffu, v, 4);
                v += __shfl_xor_sync(0xffffffffu, v, 2);
                v += __shfl_xor_sync(0xffffffffu, v, 1);
                if ((j & 31) == 0) s_red[(j >> 5) * TT + r] = v;
            }
        }
        __syncthreads();
        if (j < TT) {
            float s = 0.f;
            #pragma unroll
            for (int w = 0; w < 4; w++) s += s_red[w * TT + j];
            float inv = rsqrtf(s);
            inv = inv * (1.5f - 0.5f * s * inv * inv);  // Newton step
            s_rsq[j] = inv;
        }
        __syncthreads();
        if (g == 0) {
            #pragma unroll
            for (int r = 0; r < TT; r++) {
                int t = t0 + r;
                if (t < TOUT) {
                    float m = (t < L - 2) ? s_rsq[r] : 0.f;
                    float x, y; unpack2(acc2[r], x, y);
                    float2 o = make_float2(x * m, y * m);
                    *reinterpret_cast<float2*>(&outV[((size_t)b * TOUT + t) * HID + c0]) = o;
                }
            }
        }
    } else {
        // fully masked tile: fv rows exactly zero
        #pragma unroll
        for (int lr = 0; lr < RP; lr++) {
            int t = t0 + g * RP + lr;
            if (t < TOUT)
                *reinterpret_cast<u64*>(&outV[((size_t)b * TOUT + t) * HID + c0]) = 0ull;
        }
    }
}

// ---------------------------------------------------------------------------
extern "C" void kernel_launch(void* const* d_in, const int* in_sizes, int n_in,
                              void* d_out, int out_size)
{
    (void)in_sizes; (void)n_in; (void)out_size;
    const int*   code    = (const int*)  d_in[0];
    const float* others  = (const float*)d_in[1];
    const int*   length  = (const int*)  d_in[2];
    const int*   target  = (const int*)  d_in[3];
    const int*   widx    = (const int*)  d_in[4];
    const float* Wf      = (const float*)d_in[5];
    const float* bf      = (const float*)d_in[6];
    const float* Wb      = (const float*)d_in[7];
    const float* bb      = (const float*)d_in[8];
    const float* W0      = (const float*)d_in[9];
    const float* b0      = (const float*)d_in[10];
    const float* W1      = (const float*)d_in[11];
    const float* b1      = (const float*)d_in[12];

    float* outF = (float*)d_out;
    float* outB = outF + (size_t)BB * TOUT * HID;
    float* outV = outB + (size_t)BB * TOUT * HID;

    tgt_kernel<<<BB, 256>>>(target, widx, Wf, Wb);
    main_kernel<<<dim3(NTILE, BB), 256>>>(code, others, length,
                                          Wf, bf, Wb, bb, W0, b0, W1, b1,
                                          outF, outB, outV);
}